// round 8
// baseline (speedup 1.0000x reference)
#include <cuda_runtime.h>
#include <cuda_bf16.h>
#include <cstdint>
#include <math.h>

#define BL 512
#define DIM 512
#define NROWS 32768
#define NBLK 64

// Scratch (allocation-free rule: __device__ globals)
__device__ __nv_bfloat16 g_Xh [(size_t)NROWS*DIM];
__device__ __nv_bfloat16 g_Wth[(size_t)3*DIM*DIM];
__device__ __nv_bfloat16 g_Qh [(size_t)NROWS*DIM];
__device__ __nv_bfloat16 g_Kh [(size_t)NROWS*DIM];
__device__ __nv_bfloat16 g_Vh [(size_t)NROWS*DIM];
__device__ __nv_bfloat16 g_Ph [(size_t)NBLK*BL*BL];
__device__ float         g_S  [(size_t)NBLK*BL*BL];

// ---------------------------------------------------------------------------
__device__ __forceinline__ uint32_t smem_u32(const void* p) {
    uint32_t a;
    asm("{ .reg .u64 t; cvta.to.shared.u64 t, %1; cvt.u32.u64 %0, t; }" : "=r"(a) : "l"(p));
    return a;
}
#define CP16(dst, src) \
    asm volatile("cp.async.cg.shared.global [%0], [%1], 16;" :: "r"(dst), "l"(src))
#define CPCOMMIT() asm volatile("cp.async.commit_group;" ::: "memory")
#define CPWAIT1()  asm volatile("cp.async.wait_group 1;" ::: "memory")
#define CPWAIT0()  asm volatile("cp.async.wait_group 0;" ::: "memory")
#define LDSM4(R, addr) \
    asm volatile("ldmatrix.sync.aligned.m8n8.x4.shared.b16 {%0,%1,%2,%3}, [%4];" \
        : "=r"((R)[0]), "=r"((R)[1]), "=r"((R)[2]), "=r"((R)[3]) : "r"(addr))
#define LDSM4T(R, addr) \
    asm volatile("ldmatrix.sync.aligned.m8n8.x4.trans.shared.b16 {%0,%1,%2,%3}, [%4];" \
        : "=r"((R)[0]), "=r"((R)[1]), "=r"((R)[2]), "=r"((R)[3]) : "r"(addr))

__device__ __forceinline__ void mma16(float* c, const uint32_t* a, const uint32_t* b) {
    asm volatile(
        "mma.sync.aligned.m16n8k16.row.col.f32.bf16.bf16.f32 "
        "{%0,%1,%2,%3},{%4,%5,%6,%7},{%8,%9},{%0,%1,%2,%3};"
        : "+f"(c[0]), "+f"(c[1]), "+f"(c[2]), "+f"(c[3])
        : "r"(a[0]), "r"(a[1]), "r"(a[2]), "r"(a[3]),
          "r"(b[0]), "r"(b[1]));
}

// ---------------------------------------------------------------------------
// Layout: A/B(NT) stages 128 rows x 144 B; V(NN trans) stage 64 rows x 272 B.
// 3 stages per operand, single __syncthreads per K-chunk, prefetch depth 2.
// ---------------------------------------------------------------------------
#define ROW_BYTES   144
#define VROW_B      272
#define STAGE_BYTES (128*ROW_BYTES)   /* 18432 */
#define SMEM_BYTES  (6*STAGE_BYTES)   /* 110592 -> 2 CTAs/SM */
#define B_OFF       (3*STAGE_BYTES)

#define ACC_INIT(acc)                                         \
    float acc[2][8][4];                                       \
    _Pragma("unroll") for (int i = 0; i < 2; i++)             \
    _Pragma("unroll") for (int j = 0; j < 8; j++)             \
    _Pragma("unroll") for (int k = 0; k < 4; k++) acc[i][j][k] = 0.f;

// ---------------------------------------------------------------------------
// NT mainloop (both operands K-major): acc = A[128x512] @ B[128x512]^T
// ---------------------------------------------------------------------------
__device__ __forceinline__ void bf16_gemm_128x128(
    const __nv_bfloat16* __restrict__ A, const __nv_bfloat16* __restrict__ B,
    uint32_t sb, int tid, float acc[2][8][4])
{
    const int lane = tid & 31, wid = tid >> 5;
    const int wm = wid & 3, wn = wid >> 2;
    const int a_row = wm * 32 + (lane & 15);
    const int a_kb  = (lane >> 4) * 16;
    const int b_row = wn * 64 + ((lane >> 4) << 3) + (lane & 7);
    const int b_kb  = ((lane >> 3) & 1) * 16;
    const uint32_t a_base = sb + (uint32_t)(a_row * ROW_BYTES) + a_kb;
    const uint32_t b_base = sb + B_OFF + (uint32_t)(b_row * ROW_BYTES) + b_kb;

    auto load = [&](int c, int s) {
        const uint32_t as = sb + (uint32_t)s * STAGE_BYTES;
        const uint32_t bs = sb + B_OFF + (uint32_t)s * STAGE_BYTES;
#pragma unroll
        for (int t = 0; t < 4; t++) {
            int idx = tid + t * 256;
            int r = idx >> 3, c8 = idx & 7;
            uint32_t doff = (uint32_t)(r * ROW_BYTES + c8 * 16);
            CP16(as + doff, A + (size_t)r * DIM + c * 64 + c8 * 8);
            CP16(bs + doff, B + (size_t)r * DIM + c * 64 + c8 * 8);
        }
        CPCOMMIT();
    };

    load(0, 0);
    load(1, 1);
#pragma unroll 1
    for (int c = 0; c < 8; c++) {
        if (c < 7) CPWAIT1(); else CPWAIT0();
        __syncthreads();
        if (c + 2 < 8) load(c + 2, (c + 2) % 3);
        const int s = c % 3;
        const uint32_t aaddr = a_base + (uint32_t)s * STAGE_BYTES;
        const uint32_t baddr = b_base + (uint32_t)s * STAGE_BYTES;
#pragma unroll
        for (int ks = 0; ks < 4; ks++) {
            uint32_t af[2][4], bf[4][4];
            LDSM4(af[0], aaddr + ks * 32);
            LDSM4(af[1], aaddr + ks * 32 + 16 * ROW_BYTES);
#pragma unroll
            for (int gg = 0; gg < 4; gg++)
                LDSM4(bf[gg], baddr + ks * 32 + gg * 16 * ROW_BYTES);
#pragma unroll
            for (int mt = 0; mt < 2; mt++)
#pragma unroll
                for (int gg = 0; gg < 4; gg++) {
                    mma16(acc[mt][2 * gg + 0], af[mt], &bf[gg][0]);
                    mma16(acc[mt][2 * gg + 1], af[mt], &bf[gg][2]);
                }
        }
    }
}

// ---------------------------------------------------------------------------
// QKV: grid (4, 256, 3). C bf16 = X@Wt^T + bias
// ---------------------------------------------------------------------------
__global__ void __launch_bounds__(256, 2)
tc_gemm_qkv(const __nv_bfloat16* __restrict__ Xh, const __nv_bfloat16* __restrict__ Wth,
            const float* __restrict__ b0, const float* __restrict__ b1,
            const float* __restrict__ b2,
            __nv_bfloat16* __restrict__ Qh, __nv_bfloat16* __restrict__ Kh,
            __nv_bfloat16* __restrict__ Vh)
{
    extern __shared__ uint32_t smu[];
    const uint32_t sb = smem_u32(smu);
    const int tid = threadIdx.x;
    const int z = blockIdx.z;
    const int bm = blockIdx.y * 128, bn = blockIdx.x * 128;

    const __nv_bfloat16* A = Xh + (size_t)bm * DIM;
    const __nv_bfloat16* B = Wth + (size_t)z * DIM * DIM + (size_t)bn * DIM;
    const float* bias = (z == 0) ? b0 : (z == 1) ? b1 : b2;
    __nv_bfloat16* C = (z == 0) ? Qh : (z == 1) ? Kh : Vh;

    ACC_INIT(acc);
    bf16_gemm_128x128(A, B, sb, tid, acc);

    const int lane = tid & 31, wid = tid >> 5;
    const int wm = wid & 3, wn = wid >> 2;
    const int q = lane & 3, rg = lane >> 2;
#pragma unroll
    for (int mt = 0; mt < 2; mt++)
#pragma unroll
    for (int nt = 0; nt < 8; nt++) {
        const int rl0 = bm + wm * 32 + mt * 16 + rg;
        const int cl  = bn + wn * 64 + nt * 8 + 2 * q;
        float2 bv = *(const float2*)(bias + cl);
#pragma unroll
        for (int h = 0; h < 2; h++) {
            const int r = rl0 + h * 8;
            float v0 = acc[mt][nt][2 * h + 0] + bv.x;
            float v1 = acc[mt][nt][2 * h + 1] + bv.y;
            __nv_bfloat162 o = __float22bfloat162_rn(make_float2(v0, v1));
            *(__nv_bfloat162*)(C + (size_t)r * DIM + cl) = o;
        }
    }
}

// ---------------------------------------------------------------------------
// Scores: S fp32 = scale*(Q@K^T) + (1-mask)*(-1e10)    grid (4, 4, 64)
// ---------------------------------------------------------------------------
__global__ void __launch_bounds__(256, 2)
tc_gemm_scores(const __nv_bfloat16* __restrict__ Qg, const __nv_bfloat16* __restrict__ Kg,
               const float* __restrict__ mask, float* __restrict__ Sg)
{
    extern __shared__ uint32_t smu[];
    const uint32_t sb = smem_u32(smu);
    const int tid = threadIdx.x;
    const size_t zoff = (size_t)blockIdx.z * (BL * DIM);
    const int bm = blockIdx.y * 128, bn = blockIdx.x * 128;

    ACC_INIT(acc);
    bf16_gemm_128x128(Qg + zoff + (size_t)bm * DIM, Kg + zoff + (size_t)bn * DIM,
                      sb, tid, acc);

    const int lane = tid & 31, wid = tid >> 5;
    const int wm = wid & 3, wn = wid >> 2;
    const int q = lane & 3, rg = lane >> 2;
    const float scale = 0.04419417382415922f;  // 1/sqrt(512)
#pragma unroll
    for (int mt = 0; mt < 2; mt++)
#pragma unroll
    for (int nt = 0; nt < 8; nt++) {
        const int rl0 = bm + wm * 32 + mt * 16 + rg;
        const int cl  = bn + wn * 64 + nt * 8 + 2 * q;
#pragma unroll
        for (int h = 0; h < 2; h++) {
            const int r = rl0 + h * 8;
            const size_t base = ((size_t)blockIdx.z * BL + r) * DIM + cl;
            float2 mv = *(const float2*)(mask + base);
            float v0 = acc[mt][nt][2 * h + 0] * scale + (1.f - mv.x) * (-1e10f);
            float v1 = acc[mt][nt][2 * h + 1] * scale + (1.f - mv.y) * (-1e10f);
            *(float2*)(Sg + base) = make_float2(v0, v1);
        }
    }
}

// ---------------------------------------------------------------------------
// Output: out fp32 = P@V + X. P K-major; V consumed NN via ldmatrix.trans
// ---------------------------------------------------------------------------
__global__ void __launch_bounds__(256, 2)
tc_gemm_out(const __nv_bfloat16* __restrict__ Pg, const __nv_bfloat16* __restrict__ Vg,
            const float* __restrict__ X, float* __restrict__ out)
{
    extern __shared__ uint32_t smu[];
    const uint32_t sb = smem_u32(smu);
    const int tid = threadIdx.x;
    const int lane = tid & 31, wid = tid >> 5;
    const int wm = wid & 3, wn = wid >> 2;
    const size_t zoff = (size_t)blockIdx.z * (BL * DIM);
    const int bm = blockIdx.y * 128, bn = blockIdx.x * 128;

    const __nv_bfloat16* A = Pg + zoff + (size_t)bm * DIM;
    const __nv_bfloat16* V = Vg + zoff;

    const int a_row = wm * 32 + (lane & 15);
    const int a_kb  = (lane >> 4) * 16;
    const uint32_t a_base = sb + (uint32_t)(a_row * ROW_BYTES) + a_kb;
    const int g = lane >> 3;
    const uint32_t bt_off = (uint32_t)(((g & 1) * 8 + (lane & 7)) * VROW_B + ((g >> 1) * 8) * 2);

    ACC_INIT(acc);

    auto load = [&](int c, int s) {
        const uint32_t as = sb + (uint32_t)s * STAGE_BYTES;
        const uint32_t bs = sb + B_OFF + (uint32_t)s * STAGE_BYTES;
#pragma unroll
        for (int t = 0; t < 4; t++) {
            int idx = tid + t * 256;
            int r = idx >> 3, c8 = idx & 7;
            CP16(as + (uint32_t)(r * ROW_BYTES + c8 * 16),
                 A + (size_t)r * DIM + c * 64 + c8 * 8);
            int vr = idx >> 4, v16 = idx & 15;          // 64 rows x 16 chunks
            CP16(bs + (uint32_t)(vr * VROW_B + v16 * 16),
                 V + (size_t)(c * 64 + vr) * DIM + bn + v16 * 8);
        }
        CPCOMMIT();
    };

    load(0, 0);
    load(1, 1);
#pragma unroll 1
    for (int c = 0; c < 8; c++) {
        if (c < 7) CPWAIT1(); else CPWAIT0();
        __syncthreads();
        if (c + 2 < 8) load(c + 2, (c + 2) % 3);
        const int s = c % 3;
        const uint32_t aaddr = a_base + (uint32_t)s * STAGE_BYTES;
        const uint32_t baddr = sb + B_OFF + (uint32_t)s * STAGE_BYTES + bt_off;
#pragma unroll
        for (int ks = 0; ks < 4; ks++) {
            uint32_t af[2][4], bf[4][4];
            LDSM4(af[0], aaddr + ks * 32);
            LDSM4(af[1], aaddr + ks * 32 + 16 * ROW_BYTES);
#pragma unroll
            for (int gg = 0; gg < 4; gg++)
                LDSM4T(bf[gg], baddr + (uint32_t)(ks * 16 * VROW_B) +
                               (uint32_t)((wn * 64 + gg * 16) * 2));
#pragma unroll
            for (int mt = 0; mt < 2; mt++)
#pragma unroll
                for (int gg = 0; gg < 4; gg++) {
                    mma16(acc[mt][2 * gg + 0], af[mt], &bf[gg][0]);
                    mma16(acc[mt][2 * gg + 1], af[mt], &bf[gg][2]);
                }
        }
    }

    const int q = lane & 3, rg = lane >> 2;
#pragma unroll
    for (int mt = 0; mt < 2; mt++)
#pragma unroll
    for (int nt = 0; nt < 8; nt++) {
        const int rl0 = bm + wm * 32 + mt * 16 + rg;
        const int cl  = bn + wn * 64 + nt * 8 + 2 * q;
#pragma unroll
        for (int h = 0; h < 2; h++) {
            const int r = rl0 + h * 8;
            const size_t base = ((size_t)blockIdx.z * BL + r) * DIM + cl;
            float2 xv = *(const float2*)(X + base);
            *(float2*)(out + base) = make_float2(acc[mt][nt][2 * h + 0] + xv.x,
                                                 acc[mt][nt][2 * h + 1] + xv.y);
        }
    }
}

// ---------------------------------------------------------------------------
// fp32 -> bf16 elementwise (8 elems/thread)
// ---------------------------------------------------------------------------
__global__ __launch_bounds__(256)
void cvt_bf16(const float4* __restrict__ src, uint2* __restrict__ dst, int n8) {
    int i = blockIdx.x * 256 + threadIdx.x;
    if (i < n8) {
        float4 a = src[2 * i], b = src[2 * i + 1];
        uint2 o, o2;
        o.x = ((uint32_t)__bfloat16_as_ushort(__float2bfloat16(a.y)) << 16)
            |  (uint32_t)__bfloat16_as_ushort(__float2bfloat16(a.x));
        o.y = ((uint32_t)__bfloat16_as_ushort(__float2bfloat16(a.w)) << 16)
            |  (uint32_t)__bfloat16_as_ushort(__float2bfloat16(a.z));
        o2.x = ((uint32_t)__bfloat16_as_ushort(__float2bfloat16(b.y)) << 16)
             |  (uint32_t)__bfloat16_as_ushort(__float2bfloat16(b.x));
        o2.y = ((uint32_t)__bfloat16_as_ushort(__float2bfloat16(b.w)) << 16)
             |  (uint32_t)__bfloat16_as_ushort(__float2bfloat16(b.z));
        dst[2 * i] = o;
        dst[2 * i + 1] = o2;
    }
}

// ---------------------------------------------------------------------------
// Transpose + convert: W fp32 [512,512] -> Wt bf16 [n][k]; grid.z selects W
// ---------------------------------------------------------------------------
__global__ __launch_bounds__(256)
void wt_cvt(const float* __restrict__ w0, const float* __restrict__ w1,
            const float* __restrict__ w2, __nv_bfloat16* __restrict__ dst) {
    __shared__ float t[32][33];
    const int z = blockIdx.z;
    const float* src = (z == 0) ? w0 : (z == 1) ? w1 : w2;
    __nv_bfloat16* d = dst + (size_t)z * DIM * DIM;
    int x = blockIdx.x * 32 + threadIdx.x;
    int y = blockIdx.y * 32 + threadIdx.y;
#pragma unroll
    for (int j = 0; j < 32; j += 8)
        t[threadIdx.y + j][threadIdx.x] = src[(size_t)(y + j) * DIM + x];
    __syncthreads();
    x = blockIdx.y * 32 + threadIdx.x;
    y = blockIdx.x * 32 + threadIdx.y;
#pragma unroll
    for (int j = 0; j < 32; j += 8)
        d[(size_t)(y + j) * DIM + x] = __float2bfloat16(t[threadIdx.x][threadIdx.y + j]);
}

// ---------------------------------------------------------------------------
// Row softmax over 512 fp32 elems of g_S; writes bf16 P (g_Ph)
// ---------------------------------------------------------------------------
__global__ __launch_bounds__(128)
void softmax_rows() {
    const size_t row = blockIdx.x;
    const float4* p = (const float4*)(g_S + row * BL);
    const int tid = threadIdx.x;
    float4 v = p[tid];
    float m = fmaxf(fmaxf(v.x, v.y), fmaxf(v.z, v.w));
#pragma unroll
    for (int o = 16; o; o >>= 1) m = fmaxf(m, __shfl_xor_sync(0xFFFFFFFFu, m, o));
    __shared__ float sm[4];
    if ((tid & 31) == 0) sm[tid >> 5] = m;
    __syncthreads();
    m = fmaxf(fmaxf(sm[0], sm[1]), fmaxf(sm[2], sm[3]));
    v.x = __expf(v.x - m); v.y = __expf(v.y - m);
    v.z = __expf(v.z - m); v.w = __expf(v.w - m);
    float s = v.x + v.y + v.z + v.w;
#pragma unroll
    for (int o = 16; o; o >>= 1) s += __shfl_xor_sync(0xFFFFFFFFu, s, o);
    __shared__ float ss[4];
    if ((tid & 31) == 0) ss[tid >> 5] = s;
    __syncthreads();
    s = ss[0] + ss[1] + ss[2] + ss[3];
    float r = 1.f / s;
    __nv_bfloat162 lo = __float22bfloat162_rn(make_float2(v.x * r, v.y * r));
    __nv_bfloat162 hi = __float22bfloat162_rn(make_float2(v.z * r, v.w * r));
    uint2 o;
    o.x = *(uint32_t*)&lo;
    o.y = *(uint32_t*)&hi;
    ((uint2*)(g_Ph + row * BL))[tid] = o;
}

// ---------------------------------------------------------------------------
// LayerNorm rows in-place on d_out (eps=1e-3)
// ---------------------------------------------------------------------------
__global__ __launch_bounds__(128)
void ln_rows(float* __restrict__ out) {
    const size_t row = blockIdx.x;
    float4* p = (float4*)(out + row * DIM);
    const int tid = threadIdx.x;
    float4 v = p[tid];
    float s  = v.x + v.y + v.z + v.w;
    float sq = v.x*v.x + v.y*v.y + v.z*v.z + v.w*v.w;
#pragma unroll
    for (int o = 16; o; o >>= 1) {
        s  += __shfl_xor_sync(0xFFFFFFFFu, s,  o);
        sq += __shfl_xor_sync(0xFFFFFFFFu, sq, o);
    }
    __shared__ float ws[4], wq[4];
    if ((tid & 31) == 0) { ws[tid >> 5] = s; wq[tid >> 5] = sq; }
    __syncthreads();
    s  = ws[0] + ws[1] + ws[2] + ws[3];
    sq = wq[0] + wq[1] + wq[2] + wq[3];
    const float inv = 1.f / (float)DIM;
    float mean = s * inv;
    float var  = sq * inv - mean * mean;
    float r = rsqrtf(var + 1e-3f);
    v.x = (v.x - mean) * r; v.y = (v.y - mean) * r;
    v.z = (v.z - mean) * r; v.w = (v.w - mean) * r;
    p[tid] = v;
}

// ---------------------------------------------------------------------------
extern "C" void kernel_launch(void* const* d_in, const int* in_sizes, int n_in,
                              void* d_out, int out_size) {
    const float* X    = (const float*)d_in[0];
    const float* mask = (const float*)d_in[1];
    const float* dw1  = (const float*)d_in[2];
    const float* dw2  = (const float*)d_in[3];
    const float* dw3  = (const float*)d_in[4];
    const float* db1  = (const float*)d_in[5];
    const float* db2  = (const float*)d_in[6];
    const float* db3  = (const float*)d_in[7];
    float* out = (float*)d_out;

    __nv_bfloat16 *Xh, *Wth, *Qh, *Kh, *Vh, *Ph;
    float *S;
    cudaGetSymbolAddress((void**)&Xh,  g_Xh);
    cudaGetSymbolAddress((void**)&Wth, g_Wth);
    cudaGetSymbolAddress((void**)&Qh,  g_Qh);
    cudaGetSymbolAddress((void**)&Kh,  g_Kh);
    cudaGetSymbolAddress((void**)&Vh,  g_Vh);
    cudaGetSymbolAddress((void**)&Ph,  g_Ph);
    cudaGetSymbolAddress((void**)&S,   g_S);

    static int attr_done = 0;
    if (!attr_done) {
        cudaFuncSetAttribute(tc_gemm_qkv,    cudaFuncAttributeMaxDynamicSharedMemorySize, SMEM_BYTES);
        cudaFuncSetAttribute(tc_gemm_scores, cudaFuncAttributeMaxDynamicSharedMemorySize, SMEM_BYTES);
        cudaFuncSetAttribute(tc_gemm_out,    cudaFuncAttributeMaxDynamicSharedMemorySize, SMEM_BYTES);
        attr_done = 1;
    }

    cvt_bf16<<<(NROWS * DIM / 8 + 255) / 256, 256>>>((const float4*)X, (uint2*)Xh, NROWS * DIM / 8);
    dim3 tblk(32, 8);
    wt_cvt<<<dim3(16, 16, 3), tblk>>>(dw1, dw2, dw3, Wth);

    tc_gemm_qkv<<<dim3(4, 256, 3), 256, SMEM_BYTES>>>(Xh, Wth, db1, db2, db3, Qh, Kh, Vh);

    tc_gemm_scores<<<dim3(4, 4, NBLK), 256, SMEM_BYTES>>>(Qh, Kh, mask, S);

    softmax_rows<<<NBLK * BL, 128>>>();

    tc_gemm_out<<<dim3(4, 4, NBLK), 256, SMEM_BYTES>>>(Ph, Vh, X, out);

    ln_rows<<<NROWS, 128>>>(out);
}

// round 9
// speedup vs baseline: 1.0669x; 1.0669x over previous
#include <cuda_runtime.h>
#include <cuda_bf16.h>
#include <cstdint>
#include <math.h>

#define BL 512
#define DIM 512
#define NROWS 32768
#define NBLK 64

// Scratch (allocation-free rule: __device__ globals)
__device__ __nv_bfloat16 g_Xh [(size_t)NROWS*DIM];
__device__ __nv_bfloat16 g_Wth[(size_t)3*DIM*DIM];
__device__ __nv_bfloat16 g_Qh [(size_t)NROWS*DIM];
__device__ __nv_bfloat16 g_Kh [(size_t)NROWS*DIM];
__device__ __nv_bfloat16 g_Vh [(size_t)NROWS*DIM];
__device__ __nv_bfloat16 g_Ph [(size_t)NBLK*BL*BL];   // unnormalized exp(S), bf16

// ---------------------------------------------------------------------------
__device__ __forceinline__ uint32_t smem_u32(const void* p) {
    uint32_t a;
    asm("{ .reg .u64 t; cvta.to.shared.u64 t, %1; cvt.u32.u64 %0, t; }" : "=r"(a) : "l"(p));
    return a;
}
#define CP16(dst, src) \
    asm volatile("cp.async.cg.shared.global [%0], [%1], 16;" :: "r"(dst), "l"(src))
#define CPCOMMIT() asm volatile("cp.async.commit_group;" ::: "memory")
#define CPWAIT1()  asm volatile("cp.async.wait_group 1;" ::: "memory")
#define CPWAIT0()  asm volatile("cp.async.wait_group 0;" ::: "memory")
#define LDSM4(R, addr) \
    asm volatile("ldmatrix.sync.aligned.m8n8.x4.shared.b16 {%0,%1,%2,%3}, [%4];" \
        : "=r"((R)[0]), "=r"((R)[1]), "=r"((R)[2]), "=r"((R)[3]) : "r"(addr))
#define LDSM4T(R, addr) \
    asm volatile("ldmatrix.sync.aligned.m8n8.x4.trans.shared.b16 {%0,%1,%2,%3}, [%4];" \
        : "=r"((R)[0]), "=r"((R)[1]), "=r"((R)[2]), "=r"((R)[3]) : "r"(addr))

__device__ __forceinline__ void mma16(float* c, const uint32_t* a, const uint32_t* b) {
    asm volatile(
        "mma.sync.aligned.m16n8k16.row.col.f32.bf16.bf16.f32 "
        "{%0,%1,%2,%3},{%4,%5,%6,%7},{%8,%9},{%0,%1,%2,%3};"
        : "+f"(c[0]), "+f"(c[1]), "+f"(c[2]), "+f"(c[3])
        : "r"(a[0]), "r"(a[1]), "r"(a[2]), "r"(a[3]),
          "r"(b[0]), "r"(b[1]));
}
__device__ __forceinline__ float bf2sum(uint32_t u) {
    __nv_bfloat162 h = *(__nv_bfloat162*)&u;
    float2 f = __bfloat1622float2(h);
    return f.x + f.y;
}

// ---------------------------------------------------------------------------
// Layout: A/B(NT) stages 128 rows x 144 B; V(NN trans) stage 64 rows x 272 B.
// 2 stages (R7 structure: wait; sync; compute; sync).
// ---------------------------------------------------------------------------
#define ROW_BYTES   144
#define VROW_B      272
#define STAGE_BYTES (128*ROW_BYTES)   /* 18432 */
#define SMEM_BYTES  (4*STAGE_BYTES)   /* 73728 -> 2 CTAs/SM */

#define ACC_INIT(acc)                                         \
    float acc[2][8][4];                                       \
    _Pragma("unroll") for (int i = 0; i < 2; i++)             \
    _Pragma("unroll") for (int j = 0; j < 8; j++)             \
    _Pragma("unroll") for (int k = 0; k < 4; k++) acc[i][j][k] = 0.f;

// ---------------------------------------------------------------------------
// NT mainloop (both operands K-major): acc = A[128x512] @ B[128x512]^T
// ---------------------------------------------------------------------------
__device__ __forceinline__ void bf16_gemm_128x128(
    const __nv_bfloat16* __restrict__ A, const __nv_bfloat16* __restrict__ B,
    uint32_t sb, int tid, float acc[2][8][4])
{
    const int lane = tid & 31, wid = tid >> 5;
    const int wm = wid & 3, wn = wid >> 2;
    const int a_row = wm * 32 + (lane & 15);
    const int a_kb  = (lane >> 4) * 16;
    const int b_row = wn * 64 + ((lane >> 4) << 3) + (lane & 7);
    const int b_kb  = ((lane >> 3) & 1) * 16;
    const uint32_t a_base = sb + (uint32_t)(a_row * ROW_BYTES) + a_kb;
    const uint32_t b_base = sb + 2 * STAGE_BYTES + (uint32_t)(b_row * ROW_BYTES) + b_kb;

    auto load = [&](int c, int s) {
        const uint32_t as = sb + (uint32_t)s * STAGE_BYTES;
        const uint32_t bs = sb + (uint32_t)(2 + s) * STAGE_BYTES;
#pragma unroll
        for (int t = 0; t < 4; t++) {
            int idx = tid + t * 256;
            int r = idx >> 3, c8 = idx & 7;
            uint32_t doff = (uint32_t)(r * ROW_BYTES + c8 * 16);
            CP16(as + doff, A + (size_t)r * DIM + c * 64 + c8 * 8);
            CP16(bs + doff, B + (size_t)r * DIM + c * 64 + c8 * 8);
        }
        CPCOMMIT();
    };

    load(0, 0);
    for (int c = 0; c < 8; c++) {
        const int s = c & 1;
        if (c + 1 < 8) { load(c + 1, s ^ 1); CPWAIT1(); }
        else           { CPWAIT0(); }
        __syncthreads();
        const uint32_t aaddr = a_base + (uint32_t)s * STAGE_BYTES;
        const uint32_t baddr = b_base + (uint32_t)s * STAGE_BYTES;
#pragma unroll
        for (int ks = 0; ks < 4; ks++) {
            uint32_t af[2][4], bf[4][4];
            LDSM4(af[0], aaddr + ks * 32);
            LDSM4(af[1], aaddr + ks * 32 + 16 * ROW_BYTES);
#pragma unroll
            for (int gg = 0; gg < 4; gg++)
                LDSM4(bf[gg], baddr + ks * 32 + gg * 16 * ROW_BYTES);
#pragma unroll
            for (int mt = 0; mt < 2; mt++)
#pragma unroll
                for (int gg = 0; gg < 4; gg++) {
                    mma16(acc[mt][2 * gg + 0], af[mt], &bf[gg][0]);
                    mma16(acc[mt][2 * gg + 1], af[mt], &bf[gg][2]);
                }
        }
        __syncthreads();
    }
}

// ---------------------------------------------------------------------------
// QKV: grid (4, 256, 3). C bf16 = X@Wt^T + bias
// ---------------------------------------------------------------------------
__global__ void __launch_bounds__(256, 2)
tc_gemm_qkv(const __nv_bfloat16* __restrict__ Xh, const __nv_bfloat16* __restrict__ Wth,
            const float* __restrict__ b0, const float* __restrict__ b1,
            const float* __restrict__ b2,
            __nv_bfloat16* __restrict__ Qh, __nv_bfloat16* __restrict__ Kh,
            __nv_bfloat16* __restrict__ Vh)
{
    extern __shared__ uint32_t smu[];
    const uint32_t sb = smem_u32(smu);
    const int tid = threadIdx.x;
    const int z = blockIdx.z;
    const int bm = blockIdx.y * 128, bn = blockIdx.x * 128;

    const __nv_bfloat16* A = Xh + (size_t)bm * DIM;
    const __nv_bfloat16* B = Wth + (size_t)z * DIM * DIM + (size_t)bn * DIM;
    const float* bias = (z == 0) ? b0 : (z == 1) ? b1 : b2;
    __nv_bfloat16* C = (z == 0) ? Qh : (z == 1) ? Kh : Vh;

    ACC_INIT(acc);
    bf16_gemm_128x128(A, B, sb, tid, acc);

    const int lane = tid & 31, wid = tid >> 5;
    const int wm = wid & 3, wn = wid >> 2;
    const int q = lane & 3, rg = lane >> 2;
#pragma unroll
    for (int mt = 0; mt < 2; mt++)
#pragma unroll
    for (int nt = 0; nt < 8; nt++) {
        const int rl0 = bm + wm * 32 + mt * 16 + rg;
        const int cl  = bn + wn * 64 + nt * 8 + 2 * q;
        float2 bv = *(const float2*)(bias + cl);
#pragma unroll
        for (int h = 0; h < 2; h++) {
            const int r = rl0 + h * 8;
            float v0 = acc[mt][nt][2 * h + 0] + bv.x;
            float v1 = acc[mt][nt][2 * h + 1] + bv.y;
            __nv_bfloat162 o = __float22bfloat162_rn(make_float2(v0, v1));
            *(__nv_bfloat162*)(C + (size_t)r * DIM + cl) = o;
        }
    }
}

// ---------------------------------------------------------------------------
// Scores+exp: P bf16 = exp(scale*(Q@K^T) + (1-mask)*(-1e10))  [no-max softmax]
// grid (4, 4, 64)
// ---------------------------------------------------------------------------
__global__ void __launch_bounds__(256, 2)
tc_gemm_scores(const __nv_bfloat16* __restrict__ Qg, const __nv_bfloat16* __restrict__ Kg,
               const float* __restrict__ mask, __nv_bfloat16* __restrict__ Pg)
{
    extern __shared__ uint32_t smu[];
    const uint32_t sb = smem_u32(smu);
    const int tid = threadIdx.x;
    const size_t zoff = (size_t)blockIdx.z * (BL * DIM);
    const int bm = blockIdx.y * 128, bn = blockIdx.x * 128;

    ACC_INIT(acc);
    bf16_gemm_128x128(Qg + zoff + (size_t)bm * DIM, Kg + zoff + (size_t)bn * DIM,
                      sb, tid, acc);

    const int lane = tid & 31, wid = tid >> 5;
    const int wm = wid & 3, wn = wid >> 2;
    const int q = lane & 3, rg = lane >> 2;
    const float scale = 0.04419417382415922f;  // 1/sqrt(512)
#pragma unroll
    for (int mt = 0; mt < 2; mt++)
#pragma unroll
    for (int nt = 0; nt < 8; nt++) {
        const int rl0 = bm + wm * 32 + mt * 16 + rg;
        const int cl  = bn + wn * 64 + nt * 8 + 2 * q;
#pragma unroll
        for (int h = 0; h < 2; h++) {
            const int r = rl0 + h * 8;
            const size_t base = ((size_t)blockIdx.z * BL + r) * DIM + cl;
            float2 mv = *(const float2*)(mask + base);
            float v0 = acc[mt][nt][2 * h + 0] * scale + (1.f - mv.x) * (-1e10f);
            float v1 = acc[mt][nt][2 * h + 1] * scale + (1.f - mv.y) * (-1e10f);
            v0 = __expf(v0);
            v1 = __expf(v1);
            __nv_bfloat162 o = __float22bfloat162_rn(make_float2(v0, v1));
            *(__nv_bfloat162*)(Pg + base) = o;
        }
    }
}

// ---------------------------------------------------------------------------
// Output: out fp32 = (P@V)/rowsum(P) + X. P K-major (A operand — rowsum is
// accumulated from the A fragments); V consumed NN via ldmatrix.trans.
// grid (4, 4, 64)
// ---------------------------------------------------------------------------
__global__ void __launch_bounds__(256, 2)
tc_gemm_out(const __nv_bfloat16* __restrict__ Pg, const __nv_bfloat16* __restrict__ Vg,
            const float* __restrict__ X, float* __restrict__ out)
{
    extern __shared__ uint32_t smu[];
    const uint32_t sb = smem_u32(smu);
    const int tid = threadIdx.x;
    const int lane = tid & 31, wid = tid >> 5;
    const int wm = wid & 3, wn = wid >> 2;
    const size_t zoff = (size_t)blockIdx.z * (BL * DIM);
    const int bm = blockIdx.y * 128, bn = blockIdx.x * 128;

    const __nv_bfloat16* A = Pg + zoff + (size_t)bm * DIM;
    const __nv_bfloat16* V = Vg + zoff;

    const int a_row = wm * 32 + (lane & 15);
    const int a_kb  = (lane >> 4) * 16;
    const uint32_t a_base = sb + (uint32_t)(a_row * ROW_BYTES) + a_kb;
    const int g = lane >> 3;
    const uint32_t bt_off = (uint32_t)(((g & 1) * 8 + (lane & 7)) * VROW_B + ((g >> 1) * 8) * 2);

    ACC_INIT(acc);
    float rsum[2][2] = {{0.f, 0.f}, {0.f, 0.f}};   // [mt][h]: rows wm*32+mt*16+rg+8h

    auto load = [&](int c, int s) {
        const uint32_t as = sb + (uint32_t)s * STAGE_BYTES;
        const uint32_t bs = sb + (uint32_t)(2 + s) * STAGE_BYTES;
#pragma unroll
        for (int t = 0; t < 4; t++) {
            int idx = tid + t * 256;
            int r = idx >> 3, c8 = idx & 7;
            CP16(as + (uint32_t)(r * ROW_BYTES + c8 * 16),
                 A + (size_t)r * DIM + c * 64 + c8 * 8);
            int vr = idx >> 4, v16 = idx & 15;          // 64 rows x 16 chunks
            CP16(bs + (uint32_t)(vr * VROW_B + v16 * 16),
                 V + (size_t)(c * 64 + vr) * DIM + bn + v16 * 8);
        }
        CPCOMMIT();
    };

    load(0, 0);
    for (int c = 0; c < 8; c++) {
        const int s = c & 1;
        if (c + 1 < 8) { load(c + 1, s ^ 1); CPWAIT1(); }
        else           { CPWAIT0(); }
        __syncthreads();
        const uint32_t aaddr = a_base + (uint32_t)s * STAGE_BYTES;
        const uint32_t baddr = sb + (uint32_t)(2 + s) * STAGE_BYTES + bt_off;
#pragma unroll
        for (int ks = 0; ks < 4; ks++) {
            uint32_t af[2][4], bf[4][4];
            LDSM4(af[0], aaddr + ks * 32);
            LDSM4(af[1], aaddr + ks * 32 + 16 * ROW_BYTES);
#pragma unroll
            for (int gg = 0; gg < 4; gg++)
                LDSM4T(bf[gg], baddr + (uint32_t)(ks * 16 * VROW_B) +
                               (uint32_t)((wn * 64 + gg * 16) * 2));
#pragma unroll
            for (int mt = 0; mt < 2; mt++)
#pragma unroll
                for (int gg = 0; gg < 4; gg++) {
                    mma16(acc[mt][2 * gg + 0], af[mt], &bf[gg][0]);
                    mma16(acc[mt][2 * gg + 1], af[mt], &bf[gg][2]);
                }
            // rowsum from A fragments: a0/a2 -> row rg, a1/a3 -> row rg+8
#pragma unroll
            for (int mt = 0; mt < 2; mt++) {
                rsum[mt][0] += bf2sum(af[mt][0]) + bf2sum(af[mt][2]);
                rsum[mt][1] += bf2sum(af[mt][1]) + bf2sum(af[mt][3]);
            }
        }
        __syncthreads();
    }

    // reduce rowsum over the q lanes (lane bits 0-1), stash per-row in smem
    float* rowsum_sm = (float*)smu;                    // stages are dead now
#pragma unroll
    for (int mt = 0; mt < 2; mt++)
#pragma unroll
    for (int h = 0; h < 2; h++) {
        rsum[mt][h] += __shfl_xor_sync(0xFFFFFFFFu, rsum[mt][h], 1);
        rsum[mt][h] += __shfl_xor_sync(0xFFFFFFFFu, rsum[mt][h], 2);
    }
    const int q = lane & 3, rg = lane >> 2;
    if (wn == 0 && q == 0) {
#pragma unroll
        for (int mt = 0; mt < 2; mt++)
#pragma unroll
        for (int h = 0; h < 2; h++)
            rowsum_sm[wm * 32 + mt * 16 + rg + 8 * h] = rsum[mt][h];
    }
    __syncthreads();

#pragma unroll
    for (int mt = 0; mt < 2; mt++)
#pragma unroll
    for (int h = 0; h < 2; h++) {
        const int rl = wm * 32 + mt * 16 + rg + h * 8;
        const float inv = 1.f / rowsum_sm[rl];
        const int r = bm + rl;
#pragma unroll
        for (int nt = 0; nt < 8; nt++) {
            const int cl = bn + wn * 64 + nt * 8 + 2 * q;
            const size_t base = ((size_t)blockIdx.z * BL + r) * DIM + cl;
            float2 xv = *(const float2*)(X + base);
            *(float2*)(out + base) = make_float2(acc[mt][nt][2 * h + 0] * inv + xv.x,
                                                 acc[mt][nt][2 * h + 1] * inv + xv.y);
        }
    }
}

// ---------------------------------------------------------------------------
// fp32 -> bf16 elementwise (8 elems/thread)
// ---------------------------------------------------------------------------
__global__ __launch_bounds__(256)
void cvt_bf16(const float4* __restrict__ src, uint2* __restrict__ dst, int n8) {
    int i = blockIdx.x * 256 + threadIdx.x;
    if (i < n8) {
        float4 a = src[2 * i], b = src[2 * i + 1];
        uint2 o, o2;
        o.x = ((uint32_t)__bfloat16_as_ushort(__float2bfloat16(a.y)) << 16)
            |  (uint32_t)__bfloat16_as_ushort(__float2bfloat16(a.x));
        o.y = ((uint32_t)__bfloat16_as_ushort(__float2bfloat16(a.w)) << 16)
            |  (uint32_t)__bfloat16_as_ushort(__float2bfloat16(a.z));
        o2.x = ((uint32_t)__bfloat16_as_ushort(__float2bfloat16(b.y)) << 16)
             |  (uint32_t)__bfloat16_as_ushort(__float2bfloat16(b.x));
        o2.y = ((uint32_t)__bfloat16_as_ushort(__float2bfloat16(b.w)) << 16)
             |  (uint32_t)__bfloat16_as_ushort(__float2bfloat16(b.z));
        dst[2 * i] = o;
        dst[2 * i + 1] = o2;
    }
}

// ---------------------------------------------------------------------------
// Transpose + convert: W fp32 [512,512] -> Wt bf16 [n][k]; grid.z selects W
// ---------------------------------------------------------------------------
__global__ __launch_bounds__(256)
void wt_cvt(const float* __restrict__ w0, const float* __restrict__ w1,
            const float* __restrict__ w2, __nv_bfloat16* __restrict__ dst) {
    __shared__ float t[32][33];
    const int z = blockIdx.z;
    const float* src = (z == 0) ? w0 : (z == 1) ? w1 : w2;
    __nv_bfloat16* d = dst + (size_t)z * DIM * DIM;
    int x = blockIdx.x * 32 + threadIdx.x;
    int y = blockIdx.y * 32 + threadIdx.y;
#pragma unroll
    for (int j = 0; j < 32; j += 8)
        t[threadIdx.y + j][threadIdx.x] = src[(size_t)(y + j) * DIM + x];
    __syncthreads();
    x = blockIdx.y * 32 + threadIdx.x;
    y = blockIdx.x * 32 + threadIdx.y;
#pragma unroll
    for (int j = 0; j < 32; j += 8)
        d[(size_t)(y + j) * DIM + x] = __float2bfloat16(t[threadIdx.x][threadIdx.y + j]);
}

// ---------------------------------------------------------------------------
// LayerNorm rows in-place on d_out (eps=1e-3)
// ---------------------------------------------------------------------------
__global__ __launch_bounds__(128)
void ln_rows(float* __restrict__ out) {
    const size_t row = blockIdx.x;
    float4* p = (float4*)(out + row * DIM);
    const int tid = threadIdx.x;
    float4 v = p[tid];
    float s  = v.x + v.y + v.z + v.w;
    float sq = v.x*v.x + v.y*v.y + v.z*v.z + v.w*v.w;
#pragma unroll
    for (int o = 16; o; o >>= 1) {
        s  += __shfl_xor_sync(0xFFFFFFFFu, s,  o);
        sq += __shfl_xor_sync(0xFFFFFFFFu, sq, o);
    }
    __shared__ float ws[4], wq[4];
    if ((tid & 31) == 0) { ws[tid >> 5] = s; wq[tid >> 5] = sq; }
    __syncthreads();
    s  = ws[0] + ws[1] + ws[2] + ws[3];
    sq = wq[0] + wq[1] + wq[2] + wq[3];
    const float inv = 1.f / (float)DIM;
    float mean = s * inv;
    float var  = sq * inv - mean * mean;
    float r = rsqrtf(var + 1e-3f);
    v.x = (v.x - mean) * r; v.y = (v.y - mean) * r;
    v.z = (v.z - mean) * r; v.w = (v.w - mean) * r;
    p[tid] = v;
}

// ---------------------------------------------------------------------------
extern "C" void kernel_launch(void* const* d_in, const int* in_sizes, int n_in,
                              void* d_out, int out_size) {
    const float* X    = (const float*)d_in[0];
    const float* mask = (const float*)d_in[1];
    const float* dw1  = (const float*)d_in[2];
    const float* dw2  = (const float*)d_in[3];
    const float* dw3  = (const float*)d_in[4];
    const float* db1  = (const float*)d_in[5];
    const float* db2  = (const float*)d_in[6];
    const float* db3  = (const float*)d_in[7];
    float* out = (float*)d_out;

    __nv_bfloat16 *Xh, *Wth, *Qh, *Kh, *Vh, *Ph;
    cudaGetSymbolAddress((void**)&Xh,  g_Xh);
    cudaGetSymbolAddress((void**)&Wth, g_Wth);
    cudaGetSymbolAddress((void**)&Qh,  g_Qh);
    cudaGetSymbolAddress((void**)&Kh,  g_Kh);
    cudaGetSymbolAddress((void**)&Vh,  g_Vh);
    cudaGetSymbolAddress((void**)&Ph,  g_Ph);

    static int attr_done = 0;
    if (!attr_done) {
        cudaFuncSetAttribute(tc_gemm_qkv,    cudaFuncAttributeMaxDynamicSharedMemorySize, SMEM_BYTES);
        cudaFuncSetAttribute(tc_gemm_scores, cudaFuncAttributeMaxDynamicSharedMemorySize, SMEM_BYTES);
        cudaFuncSetAttribute(tc_gemm_out,    cudaFuncAttributeMaxDynamicSharedMemorySize, SMEM_BYTES);
        attr_done = 1;
    }

    cvt_bf16<<<(NROWS * DIM / 8 + 255) / 256, 256>>>((const float4*)X, (uint2*)Xh, NROWS * DIM / 8);
    dim3 tblk(32, 8);
    wt_cvt<<<dim3(16, 16, 3), tblk>>>(dw1, dw2, dw3, Wth);

    tc_gemm_qkv<<<dim3(4, 256, 3), 256, SMEM_BYTES>>>(Xh, Wth, db1, db2, db3, Qh, Kh, Vh);

    tc_gemm_scores<<<dim3(4, 4, NBLK), 256, SMEM_BYTES>>>(Qh, Kh, mask, Ph);

    tc_gemm_out<<<dim3(4, 4, NBLK), 256, SMEM_BYTES>>>(Ph, Vh, X, out);

    ln_rows<<<NROWS, 128>>>(out);
}